// round 2
// baseline (speedup 1.0000x reference)
#include <cuda_runtime.h>
#include <cuda_bf16.h>
#include <cstdint>

#define S    1024
#define D    1024
#define PP   2816
#define R    64
#define E    8
#define MM   16
#define SPAD 1152
#define NT   (SPAD/16)   // 72 sixteen-row tiles

// ---------------- device scratch (static, no runtime alloc) ----------------
__device__ float g_alpha[2][E][MM];          // softmax mixture weights (0=up,1=gate)
__device__ float g_up_mixed[E*D*R];          // [E][D][R]
__device__ float g_gate_mixed[E*D*R];
__device__ float g_aut[E*R*PP];              // transposed up adapters [E][R][P]
__device__ float g_agt[E*R*PP];              // transposed gate adapters
__device__ int   g_perm[SPAD];               // permuted row -> token (or -1 pad)
__device__ float g_wrow[SPAD];               // routing weight per permuted row
__device__ int   g_poff[E+1];                // padded expert offsets (mult of 16)
__device__ int   g_etile[NT];                // expert per 16-row tile (or -1)
__device__ float g_tpart[4*SPAD*2*R];        // split-K partials of t (up|gate)
__device__ float g_inter[SPAD*PP];           // silu(gate)*up, tf32-rounded fp32

// ---------------- K1: routing, permutation, alphas ----------------
__global__ __launch_bounds__(1024) void k_route(const int* __restrict__ eidx,
                                                const float* __restrict__ ew,
                                                const float* __restrict__ ulog,
                                                const float* __restrict__ glog) {
    __shared__ int wcnt[32][E];
    __shared__ int woff[32][E];
    __shared__ int poff_s[E+1];
    int t = threadIdx.x;
    int e = eidx[t];                      // K = 1
    int w = t >> 5, lane = t & 31;
    if (lane < E) wcnt[w][lane] = 0;
    __syncthreads();
    unsigned mask = __match_any_sync(0xffffffffu, e);
    int posw = __popc(mask & ((1u << lane) - 1u));
    if (posw == 0) wcnt[w][e] = __popc(mask);
    __syncthreads();
    if (t < 256) {                        // exclusive prefix over warps per expert
        int e2 = t >> 5, w2 = t & 31;
        int sacc = 0;
        for (int ww = 0; ww < w2; ww++) sacc += wcnt[ww][e2];
        woff[w2][e2] = sacc;
    }
    __syncthreads();
    if (t == 0) {
        int o = 0;
        for (int e2 = 0; e2 < E; e2++) {
            poff_s[e2] = o;
            int c = woff[31][e2] + wcnt[31][e2];
            o += (c + 15) & ~15;          // pad each expert to 16 rows
        }
        poff_s[E] = o;
        for (int i = 0; i <= E; i++) g_poff[i] = poff_s[i];
    }
    __syncthreads();
    for (int i = t; i < SPAD; i += 1024) { g_perm[i] = -1; g_wrow[i] = 0.f; }
    __syncthreads();
    int row = poff_s[e] + woff[w][e] + posw;
    g_perm[row] = t;
    g_wrow[row] = ew[t];
    if (t < NT) {
        int r0 = t * 16; int ee = -1;
        for (int e2 = 0; e2 < E; e2++)
            if (r0 >= poff_s[e2] && r0 < poff_s[e2+1]) ee = e2;
        g_etile[t] = ee;
    }
    if (t < 2 * E) {                      // softmax over M=16
        int which = t & 1, e2 = t >> 1;
        const float* L = (which ? glog : ulog) + e2 * MM;
        float mx = L[0];
        for (int m = 1; m < MM; m++) mx = fmaxf(mx, L[m]);
        float sum = 0.f, ex[MM];
        for (int m = 0; m < MM; m++) { ex[m] = __expf(L[m] - mx); sum += ex[m]; }
        float inv = 1.f / sum;
        for (int m = 0; m < MM; m++) g_alpha[which][e2][m] = ex[m] * inv;
    }
}

// ---------------- K2: mixed bases [E,D,R] = alpha @ bank ----------------
__global__ __launch_bounds__(256) void k_mixed(const float* __restrict__ ubank,
                                               const float* __restrict__ gbank) {
    __shared__ float al[2 * E * MM];      // 256 floats
    int t = threadIdx.x;
    al[t] = ((const float*)g_alpha)[t];
    __syncthreads();
    int r = t & 63, dl = t >> 6;
    int d = blockIdx.x * 4 + dl;
    float au[E], ag[E];
    #pragma unroll
    for (int e = 0; e < E; e++) { au[e] = 0.f; ag[e] = 0.f; }
    #pragma unroll
    for (int m = 0; m < MM; m++) {
        float bu = ubank[(m * D + d) * R + r];
        float bg = gbank[(m * D + d) * R + r];
        #pragma unroll
        for (int e = 0; e < E; e++) {
            au[e] += al[e * MM + m] * bu;
            ag[e] += al[E * MM + e * MM + m] * bg;
        }
    }
    #pragma unroll
    for (int e = 0; e < E; e++) {
        g_up_mixed  [(e * D + d) * R + r] = au[e];
        g_gate_mixed[(e * D + d) * R + r] = ag[e];
    }
}

// ---------------- K2b: transpose adapters [E,P,R] -> [E,R,P] ----------------
__global__ __launch_bounds__(256) void k_trans(const float* __restrict__ uA,
                                               const float* __restrict__ gA) {
    int e = blockIdx.z >> 1, which = blockIdx.z & 1;
    const float* src = which ? gA : uA;
    float* dst = which ? g_agt : g_aut;
    int p0 = blockIdx.x * 32, r0 = blockIdx.y * 32;
    __shared__ float sm[32][33];
    int tx = threadIdx.x, ty = threadIdx.y;
    for (int i = ty; i < 32; i += 8)
        sm[i][tx] = src[(e * PP + p0 + i) * R + r0 + tx];
    __syncthreads();
    for (int i = ty; i < 32; i += 8)
        dst[(e * R + r0 + i) * PP + p0 + tx] = sm[tx][i];
}

// ---------------- K3: t = X_gathered @ mixed (split-K=4 partials) ----------------
__global__ __launch_bounds__(256) void k_tproj(const float* __restrict__ x) {
    int tile = blockIdx.x;
    int e = g_etile[tile];
    if (e < 0) return;
    int split = blockIdx.y, d0 = split * 256;
    int base = tile * 16;
    __shared__ float xs[16 * 256];
    __shared__ int ps[16];
    int t = threadIdx.x;
    if (t < 16) ps[t] = g_perm[base + t];
    __syncthreads();
    #pragma unroll
    for (int i = 0; i < 4; i++) {
        int q = t + i * 256;              // float4 index over 16x256
        int row = q >> 6, qd = q & 63;
        int s = ps[row];
        float4 v = make_float4(0.f, 0.f, 0.f, 0.f);
        if (s >= 0) v = *(const float4*)&x[s * D + d0 + qd * 4];
        *(float4*)&xs[row * 256 + qd * 4] = v;
    }
    __syncthreads();
    int r = t & 63, tg = t >> 6;
    float au[4] = {0.f,0.f,0.f,0.f}, ag[4] = {0.f,0.f,0.f,0.f};
    const float* mu = &g_up_mixed  [(e * D + d0) * R + r];
    const float* mg = &g_gate_mixed[(e * D + d0) * R + r];
    for (int d = 0; d < 256; d++) {
        float u = mu[d * R], g2 = mg[d * R];
        #pragma unroll
        for (int i = 0; i < 4; i++) {
            float xv = xs[(tg * 4 + i) * 256 + d];
            au[i] += xv * u; ag[i] += xv * g2;
        }
    }
    #pragma unroll
    for (int i = 0; i < 4; i++) {
        int row = base + tg * 4 + i;
        g_tpart[(split * SPAD + row) * 128 + r]      = au[i];
        g_tpart[(split * SPAD + row) * 128 + 64 + r] = ag[i];
    }
}

// ---------------- K4: up/gate via adapters + silu, tf32-rounded inter ----------------
__global__ __launch_bounds__(256) void k_adapt() {
    int tile = blockIdx.x;
    int e = g_etile[tile];
    if (e < 0) return;
    int p0 = blockIdx.y * 256;
    int base = tile * 16;
    __shared__ float ts[16 * 128];
    int t = threadIdx.x;
    #pragma unroll
    for (int i = 0; i < 2; i++) {         // reduce 4 split-K partials
        int q = t + i * 256;              // float4 over 16x128
        int row = q >> 5, c4 = q & 31;
        float4 acc = make_float4(0.f, 0.f, 0.f, 0.f);
        #pragma unroll
        for (int sp = 0; sp < 4; sp++) {
            float4 v = *(const float4*)&g_tpart[(sp * SPAD + base + row) * 128 + c4 * 4];
            acc.x += v.x; acc.y += v.y; acc.z += v.z; acc.w += v.w;
        }
        *(float4*)&ts[row * 128 + c4 * 4] = acc;
    }
    __syncthreads();
    int j = t & 63, tg = t >> 6;
    float accu[4][4] = {}, accg[4][4] = {};
    const float* aup = &g_aut[(e * R) * PP + p0 + j * 4];
    const float* agp = &g_agt[(e * R) * PP + p0 + j * 4];
    #pragma unroll 4
    for (int r = 0; r < R; r++) {
        float4 au  = *(const float4*)&aup[r * PP];
        float4 ag4 = *(const float4*)&agp[r * PP];
        #pragma unroll
        for (int i = 0; i < 4; i++) {
            float tu  = ts[(tg * 4 + i) * 128 + r];
            float tg2 = ts[(tg * 4 + i) * 128 + 64 + r];
            accu[i][0] += tu * au.x;  accu[i][1] += tu * au.y;
            accu[i][2] += tu * au.z;  accu[i][3] += tu * au.w;
            accg[i][0] += tg2 * ag4.x; accg[i][1] += tg2 * ag4.y;
            accg[i][2] += tg2 * ag4.z; accg[i][3] += tg2 * ag4.w;
        }
    }
    #pragma unroll
    for (int i = 0; i < 4; i++) {
        int row = base + tg * 4 + i;
        float4 o;
        #pragma unroll
        for (int c = 0; c < 4; c++) {
            float gv = accg[i][c], uv = accu[i][c];
            float sv = uv * gv / (1.f + __expf(-gv));   // up * silu(gate)
            unsigned b; asm("cvt.rna.tf32.f32 %0, %1;" : "=r"(b) : "f"(sv));
            ((float*)&o)[c] = __uint_as_float(b);
        }
        *(float4*)&g_inter[row * PP + p0 + j * 4] = o;
    }
}

// ---------------- K5: routed down GEMM, tf32 mma, cp.async pipeline ----------------
#define TK 16
__global__ __launch_bounds__(256) void k_down(const float* __restrict__ down,
                                              float* __restrict__ out) {
    int e = blockIdx.z;
    int r0 = g_poff[e], r1 = g_poff[e + 1];
    int rowBase = r0 + blockIdx.y * 128;
    if (rowBase >= r1) return;
    int rem = min(128, r1 - rowBase);
    int d0 = blockIdx.x * 64;
    const float* Ag = g_inter + (size_t)rowBase * PP;
    const float* Bg = down + ((size_t)e * D + d0) * PP;
    __shared__ float As[3][128 * 20];     // stride 20: conflict-free, 16B-aligned rows
    __shared__ float Bs[3][64 * 20];
    int t = threadIdx.x;

    auto issue = [&](int kt, int buf) {
        int kk = kt * TK;
        #pragma unroll
        for (int i = 0; i < 2; i++) {
            int idx = t + i * 256;
            int row = idx >> 2, c4 = idx & 3;
            const float* src = Ag + (size_t)row * PP + kk + c4 * 4;
            bool ok = row < rem;
            unsigned sa = (unsigned)__cvta_generic_to_shared(&As[buf][row * 20 + c4 * 4]);
            int sz = ok ? 16 : 0;
            asm volatile("cp.async.cg.shared.global [%0], [%1], 16, %2;"
                         :: "r"(sa), "l"(ok ? src : Ag), "r"(sz));
        }
        {
            int row = t >> 2, c4 = t & 3;
            const float* src = Bg + (size_t)row * PP + kk + c4 * 4;
            unsigned sa = (unsigned)__cvta_generic_to_shared(&Bs[buf][row * 20 + c4 * 4]);
            asm volatile("cp.async.cg.shared.global [%0], [%1], 16, %2;"
                         :: "r"(sa), "l"(src), "r"(16));
        }
        asm volatile("cp.async.commit_group;");
    };

    issue(0, 0); issue(1, 1);
    float acc[2][4][4] = {};
    int lane = t & 31, g = lane >> 2, tq = lane & 3;
    int warp = t >> 5, wm = warp & 3, wn = warp >> 2;
    const int NKT = PP / TK;              // 176

    for (int kt = 0; kt < NKT; kt++) {
        if (kt + 2 < NKT) { asm volatile("cp.async.wait_group 1;"); }
        else              { asm volatile("cp.async.wait_group 0;"); }
        __syncthreads();
        if (kt + 2 < NKT) issue(kt + 2, (kt + 2) % 3);
        const float* Ab = As[kt % 3];
        const float* Bb = Bs[kt % 3];
        #pragma unroll
        for (int ks = 0; ks < 2; ks++) {
            int kb = ks * 8;
            unsigned a[2][4], b[4][2];
            #pragma unroll
            for (int mf = 0; mf < 2; mf++) {
                int mr = wm * 32 + mf * 16 + g;
                a[mf][0] = __float_as_uint(Ab[ mr      * 20 + kb + tq]);
                a[mf][1] = __float_as_uint(Ab[(mr + 8) * 20 + kb + tq]);
                a[mf][2] = __float_as_uint(Ab[ mr      * 20 + kb + tq + 4]);
                a[mf][3] = __float_as_uint(Ab[(mr + 8) * 20 + kb + tq + 4]);
            }
            #pragma unroll
            for (int nf = 0; nf < 4; nf++) {
                int nr = wn * 32 + nf * 8 + g;
                b[nf][0] = __float_as_uint(Bb[nr * 20 + kb + tq]);
                b[nf][1] = __float_as_uint(Bb[nr * 20 + kb + tq + 4]);
            }
            #pragma unroll
            for (int mf = 0; mf < 2; mf++)
                #pragma unroll
                for (int nf = 0; nf < 4; nf++)
                    asm volatile(
                        "mma.sync.aligned.m16n8k8.row.col.f32.tf32.tf32.f32 "
                        "{%0,%1,%2,%3}, {%4,%5,%6,%7}, {%8,%9}, {%0,%1,%2,%3};"
                        : "+f"(acc[mf][nf][0]), "+f"(acc[mf][nf][1]),
                          "+f"(acc[mf][nf][2]), "+f"(acc[mf][nf][3])
                        : "r"(a[mf][0]), "r"(a[mf][1]), "r"(a[mf][2]), "r"(a[mf][3]),
                          "r"(b[nf][0]), "r"(b[nf][1]));
        }
    }
    // epilogue: scale by routing weight, scatter to original token rows
    #pragma unroll
    for (int mf = 0; mf < 2; mf++) {
        #pragma unroll
        for (int h = 0; h < 2; h++) {
            int m = wm * 32 + mf * 16 + g + h * 8;
            if (m < rem) {
                int s = g_perm[rowBase + m];
                if (s >= 0) {
                    float wv = g_wrow[rowBase + m];
                    #pragma unroll
                    for (int nf = 0; nf < 4; nf++) {
                        int n = d0 + wn * 32 + nf * 8 + tq * 2;
                        float2 v;
                        v.x = acc[mf][nf][h * 2 + 0] * wv;
                        v.y = acc[mf][nf][h * 2 + 1] * wv;
                        *(float2*)&out[(size_t)s * D + n] = v;
                    }
                }
            }
        }
    }
}

// ---------------- launch ----------------
extern "C" void kernel_launch(void* const* d_in, const int* in_sizes, int n_in,
                              void* d_out, int out_size) {
    const float* x     = (const float*)d_in[0];
    const int*   eidx  = (const int*)  d_in[1];
    const float* ew    = (const float*)d_in[2];
    const float* uA    = (const float*)d_in[3];
    const float* gA    = (const float*)d_in[4];
    const float* ulog  = (const float*)d_in[5];
    const float* glog  = (const float*)d_in[6];
    const float* down  = (const float*)d_in[7];
    const float* ubank = (const float*)d_in[8];
    const float* gbank = (const float*)d_in[9];
    float* out = (float*)d_out;

    k_route<<<1, 1024>>>(eidx, ew, ulog, glog);
    k_mixed<<<256, 256>>>(ubank, gbank);
    k_trans<<<dim3(PP / 32, R / 32, 2 * E), dim3(32, 8)>>>(uA, gA);
    k_tproj<<<dim3(NT, 4), 256>>>(x);
    k_adapt<<<dim3(NT, PP / 256), 256>>>();
    k_down<<<dim3(D / 64, 8, E), 256>>>(down, out);
}

// round 4
// speedup vs baseline: 1.2528x; 1.2528x over previous
#include <cuda_runtime.h>
#include <cuda_bf16.h>
#include <cstdint>

#define S    1024
#define D    1024
#define PP   2816
#define R    64
#define E    8
#define MM   16
#define SPAD 1152
#define NT   (SPAD/16)   // 72 sixteen-row tiles

// ---------------- device scratch (static, no runtime alloc) ----------------
__device__ float g_alpha[2][E][MM];          // softmax mixture weights (0=up,1=gate)
__device__ float g_up_mixed[E*D*R];          // [E][D][R]
__device__ float g_gate_mixed[E*D*R];
__device__ float g_aut[E*R*PP];              // transposed up adapters [E][R][P]
__device__ float g_agt[E*R*PP];              // transposed gate adapters
__device__ int   g_perm[SPAD];               // permuted row -> token (or -1 pad)
__device__ float g_wrow[SPAD];               // routing weight per permuted row
__device__ int   g_poff[E+1];                // padded expert offsets (mult of 16)
__device__ int   g_etile[NT];                // expert per 16-row tile (or -1)
__device__ float g_tpart[4*SPAD*2*R];        // split-K partials of t (up|gate)
__device__ float g_inter[SPAD*PP];           // silu(gate)*up, tf32-rounded fp32

// ---------------- K1: routing, permutation, alphas ----------------
__global__ __launch_bounds__(1024) void k_route(const int* __restrict__ eidx,
                                                const float* __restrict__ ew,
                                                const float* __restrict__ ulog,
                                                const float* __restrict__ glog) {
    __shared__ int wcnt[32][E];
    __shared__ int woff[32][E];
    __shared__ int poff_s[E+1];
    int t = threadIdx.x;
    int e = eidx[t];                      // K = 1
    int w = t >> 5, lane = t & 31;
    if (lane < E) wcnt[w][lane] = 0;
    __syncthreads();
    unsigned mask = __match_any_sync(0xffffffffu, e);
    int posw = __popc(mask & ((1u << lane) - 1u));
    if (posw == 0) wcnt[w][e] = __popc(mask);
    __syncthreads();
    if (t < 256) {                        // exclusive prefix over warps per expert
        int e2 = t >> 5, w2 = t & 31;
        int sacc = 0;
        for (int ww = 0; ww < w2; ww++) sacc += wcnt[ww][e2];
        woff[w2][e2] = sacc;
    }
    __syncthreads();
    if (t == 0) {
        int o = 0;
        for (int e2 = 0; e2 < E; e2++) {
            poff_s[e2] = o;
            int c = woff[31][e2] + wcnt[31][e2];
            o += (c + 15) & ~15;          // pad each expert to 16 rows
        }
        poff_s[E] = o;
        for (int i = 0; i <= E; i++) g_poff[i] = poff_s[i];
    }
    __syncthreads();
    for (int i = t; i < SPAD; i += 1024) { g_perm[i] = -1; g_wrow[i] = 0.f; }
    __syncthreads();
    int row = poff_s[e] + woff[w][e] + posw;
    g_perm[row] = t;
    g_wrow[row] = ew[t];
    if (t < NT) {
        int r0 = t * 16; int ee = -1;
        for (int e2 = 0; e2 < E; e2++)
            if (r0 >= poff_s[e2] && r0 < poff_s[e2+1]) ee = e2;
        g_etile[t] = ee;
    }
    if (t < 2 * E) {                      // softmax over M=16
        int which = t & 1, e2 = t >> 1;
        const float* L = (which ? glog : ulog) + e2 * MM;
        float mx = L[0];
        for (int m = 1; m < MM; m++) mx = fmaxf(mx, L[m]);
        float sum = 0.f, ex[MM];
        for (int m = 0; m < MM; m++) { ex[m] = __expf(L[m] - mx); sum += ex[m]; }
        float inv = 1.f / sum;
        for (int m = 0; m < MM; m++) g_alpha[which][e2][m] = ex[m] * inv;
    }
}

// ---------------- K2: mixed bases [E,D,R] = alpha @ bank ----------------
__global__ __launch_bounds__(256) void k_mixed(const float* __restrict__ ubank,
                                               const float* __restrict__ gbank) {
    __shared__ float al[2 * E * MM];      // 256 floats
    int t = threadIdx.x;
    al[t] = ((const float*)g_alpha)[t];
    __syncthreads();
    int r = t & 63, dl = t >> 6;
    int d = blockIdx.x * 4 + dl;
    float au[E], ag[E];
    #pragma unroll
    for (int e = 0; e < E; e++) { au[e] = 0.f; ag[e] = 0.f; }
    #pragma unroll
    for (int m = 0; m < MM; m++) {
        float bu = ubank[(m * D + d) * R + r];
        float bg = gbank[(m * D + d) * R + r];
        #pragma unroll
        for (int e = 0; e < E; e++) {
            au[e] += al[e * MM + m] * bu;
            ag[e] += al[E * MM + e * MM + m] * bg;
        }
    }
    #pragma unroll
    for (int e = 0; e < E; e++) {
        g_up_mixed  [(e * D + d) * R + r] = au[e];
        g_gate_mixed[(e * D + d) * R + r] = ag[e];
    }
}

// ---------------- K2b: transpose adapters [E,P,R] -> [E,R,P] ----------------
__global__ __launch_bounds__(256) void k_trans(const float* __restrict__ uA,
                                               const float* __restrict__ gA) {
    int e = blockIdx.z >> 1, which = blockIdx.z & 1;
    const float* src = which ? gA : uA;
    float* dst = which ? g_agt : g_aut;
    int p0 = blockIdx.x * 32, r0 = blockIdx.y * 32;
    __shared__ float sm[32][33];
    int tx = threadIdx.x, ty = threadIdx.y;
    for (int i = ty; i < 32; i += 8)
        sm[i][tx] = src[(e * PP + p0 + i) * R + r0 + tx];
    __syncthreads();
    for (int i = ty; i < 32; i += 8)
        dst[(e * R + r0 + i) * PP + p0 + tx] = sm[tx][i];
}

// ---------------- K3: t = X_gathered @ mixed (split-K=4, pipelined smem) ----------------
#define TCK 32
__global__ __launch_bounds__(256) void k_tproj(const float* __restrict__ x) {
    int tile = blockIdx.x;
    int e = g_etile[tile];
    if (e < 0) return;
    int split = blockIdx.y, d0 = split * 256;
    int base = tile * 16;
    __shared__ float xs[16][256];         // X tile, d-contiguous per row
    __shared__ float ms[3][TCK][128];     // mixed chunks: [d][col] col<64 up, >=64 gate
    __shared__ int ps[16];
    int t = threadIdx.x;
    if (t < 16) ps[t] = g_perm[base + t];
    __syncthreads();

    // X tile via cp.async (one group): 16 rows x 64 f4
    #pragma unroll
    for (int i = 0; i < 4; i++) {
        int q = t + i * 256;
        int row = q >> 6, c4 = q & 63;
        int s = ps[row];
        unsigned sa = (unsigned)__cvta_generic_to_shared(&xs[row][c4 * 4]);
        const float* src = &x[(size_t)(s < 0 ? 0 : s) * D + d0 + c4 * 4];
        int sz = (s >= 0) ? 16 : 0;
        asm volatile("cp.async.cg.shared.global [%0], [%1], 16, %2;"
                     :: "r"(sa), "l"(src), "r"(sz));
    }
    asm volatile("cp.async.commit_group;");

    const float* upb = g_up_mixed   + (size_t)(e * D + d0) * R;
    const float* gtb = g_gate_mixed + (size_t)(e * D + d0) * R;
    auto load_ms = [&](int ck, int buf) {
        #pragma unroll
        for (int i = 0; i < 4; i++) {
            int q = t + i * 256;          // 1024 f4 slots = 32 d x 32 f4
            int d = q >> 5, c = q & 31;   // c<16: up r-slot, c>=16: gate r-slot
            const float* src = (c < 16)
                ? upb + (size_t)(ck * TCK + d) * R + c * 4
                : gtb + (size_t)(ck * TCK + d) * R + (c - 16) * 4;
            unsigned sa = (unsigned)__cvta_generic_to_shared(&ms[buf][d][c * 4]);
            asm volatile("cp.async.cg.shared.global [%0], [%1], 16, 16;"
                         :: "r"(sa), "l"(src));
        }
        asm volatile("cp.async.commit_group;");
    };

    load_ms(0, 0);
    load_ms(1, 1);

    int col = t & 127, rg = t >> 7;       // col: 0-63 up, 64-127 gate; rg: row group
    float acc[8] = {};
    const int NCK = 256 / TCK;            // 8 chunks

    for (int ck = 0; ck < NCK; ck++) {
        if (ck + 2 < NCK) { asm volatile("cp.async.wait_group 1;"); }
        else              { asm volatile("cp.async.wait_group 0;"); }
        __syncthreads();
        if (ck + 2 < NCK) load_ms(ck + 2, (ck + 2) % 3);
        const float (*mb)[128] = ms[ck % 3];
        #pragma unroll
        for (int dd = 0; dd < TCK; dd += 4) {
            float4 xv[8];
            #pragma unroll
            for (int i = 0; i < 8; i++)
                xv[i] = *(const float4*)&xs[rg * 8 + i][ck * TCK + dd];
            #pragma unroll
            for (int j = 0; j < 4; j++) {
                float m = mb[dd + j][col];
                #pragma unroll
                for (int i = 0; i < 8; i++)
                    acc[i] += ((const float*)&xv[i])[j] * m;
            }
        }
        __syncthreads();
    }
    #pragma unroll
    for (int i = 0; i < 8; i++)
        g_tpart[(size_t)(split * SPAD + base + rg * 8 + i) * 128 + col] = acc[i];
}

// ---------------- K4: up/gate via adapters + silu, tf32-rounded inter ----------------
__global__ __launch_bounds__(256) void k_adapt() {
    int tile = blockIdx.x;
    int e = g_etile[tile];
    if (e < 0) return;
    int p0 = blockIdx.y * 256;
    int base = tile * 16;
    __shared__ float ts[16 * 128];
    int t = threadIdx.x;
    #pragma unroll
    for (int i = 0; i < 2; i++) {         // reduce 4 split-K partials
        int q = t + i * 256;              // float4 over 16x128
        int row = q >> 5, c4 = q & 31;
        float4 acc = make_float4(0.f, 0.f, 0.f, 0.f);
        #pragma unroll
        for (int sp = 0; sp < 4; sp++) {
            float4 v = *(const float4*)&g_tpart[(sp * SPAD + base + row) * 128 + c4 * 4];
            acc.x += v.x; acc.y += v.y; acc.z += v.z; acc.w += v.w;
        }
        *(float4*)&ts[row * 128 + c4 * 4] = acc;
    }
    __syncthreads();
    int j = t & 63, tg = t >> 6;
    float accu[4][4] = {}, accg[4][4] = {};
    const float* aup = &g_aut[(e * R) * PP + p0 + j * 4];
    const float* agp = &g_agt[(e * R) * PP + p0 + j * 4];
    #pragma unroll 4
    for (int r = 0; r < R; r++) {
        float4 au  = *(const float4*)&aup[r * PP];
        float4 ag4 = *(const float4*)&agp[r * PP];
        #pragma unroll
        for (int i = 0; i < 4; i++) {
            float tu  = ts[(tg * 4 + i) * 128 + r];
            float tg2 = ts[(tg * 4 + i) * 128 + 64 + r];
            accu[i][0] += tu * au.x;  accu[i][1] += tu * au.y;
            accu[i][2] += tu * au.z;  accu[i][3] += tu * au.w;
            accg[i][0] += tg2 * ag4.x; accg[i][1] += tg2 * ag4.y;
            accg[i][2] += tg2 * ag4.z; accg[i][3] += tg2 * ag4.w;
        }
    }
    #pragma unroll
    for (int i = 0; i < 4; i++) {
        int row = base + tg * 4 + i;
        float4 o;
        #pragma unroll
        for (int c = 0; c < 4; c++) {
            float gv = accg[i][c], uv = accu[i][c];
            float sv = uv * gv / (1.f + __expf(-gv));   // up * silu(gate)
            unsigned b; asm("cvt.rna.tf32.f32 %0, %1;" : "=r"(b) : "f"(sv));
            ((float*)&o)[c] = __uint_as_float(b);
        }
        *(float4*)&g_inter[row * PP + p0 + j * 4] = o;
    }
}

// ---------------- K5: routed down GEMM, tf32 mma, cp.async pipeline ----------------
#define TK 16
__global__ __launch_bounds__(256) void k_down(const float* __restrict__ down,
                                              float* __restrict__ out) {
    int e = blockIdx.z;
    int r0 = g_poff[e], r1 = g_poff[e + 1];
    int rowBase = r0 + blockIdx.y * 128;
    if (rowBase >= r1) return;
    int rem = min(128, r1 - rowBase);
    int d0 = blockIdx.x * 64;
    const float* Ag = g_inter + (size_t)rowBase * PP;
    const float* Bg = down + ((size_t)e * D + d0) * PP;
    __shared__ float As[3][128 * 20];     // stride 20: conflict-free, 16B-aligned rows
    __shared__ float Bs[3][64 * 20];
    int t = threadIdx.x;

    auto issue = [&](int kt, int buf) {
        int kk = kt * TK;
        #pragma unroll
        for (int i = 0; i < 2; i++) {
            int idx = t + i * 256;
            int row = idx >> 2, c4 = idx & 3;
            const float* src = Ag + (size_t)row * PP + kk + c4 * 4;
            bool ok = row < rem;
            unsigned sa = (unsigned)__cvta_generic_to_shared(&As[buf][row * 20 + c4 * 4]);
            int sz = ok ? 16 : 0;
            asm volatile("cp.async.cg.shared.global [%0], [%1], 16, %2;"
                         :: "r"(sa), "l"(ok ? src : Ag), "r"(sz));
        }
        {
            int row = t >> 2, c4 = t & 3;
            const float* src = Bg + (size_t)row * PP + kk + c4 * 4;
            unsigned sa = (unsigned)__cvta_generic_to_shared(&Bs[buf][row * 20 + c4 * 4]);
            asm volatile("cp.async.cg.shared.global [%0], [%1], 16, %2;"
                         :: "r"(sa), "l"(src), "r"(16));
        }
        asm volatile("cp.async.commit_group;");
    };

    issue(0, 0); issue(1, 1);
    float acc[2][4][4] = {};
    int lane = t & 31, g = lane >> 2, tq = lane & 3;
    int warp = t >> 5, wm = warp & 3, wn = warp >> 2;
    const int NKT = PP / TK;              // 176

    for (int kt = 0; kt < NKT; kt++) {
        if (kt + 2 < NKT) { asm volatile("cp.async.wait_group 1;"); }
        else              { asm volatile("cp.async.wait_group 0;"); }
        __syncthreads();
        if (kt + 2 < NKT) issue(kt + 2, (kt + 2) % 3);
        const float* Ab = As[kt % 3];
        const float* Bb = Bs[kt % 3];
        #pragma unroll
        for (int ks = 0; ks < 2; ks++) {
            int kb = ks * 8;
            unsigned a[2][4], b[4][2];
            #pragma unroll
            for (int mf = 0; mf < 2; mf++) {
                int mr = wm * 32 + mf * 16 + g;
                a[mf][0] = __float_as_uint(Ab[ mr      * 20 + kb + tq]);
                a[mf][1] = __float_as_uint(Ab[(mr + 8) * 20 + kb + tq]);
                a[mf][2] = __float_as_uint(Ab[ mr      * 20 + kb + tq + 4]);
                a[mf][3] = __float_as_uint(Ab[(mr + 8) * 20 + kb + tq + 4]);
            }
            #pragma unroll
            for (int nf = 0; nf < 4; nf++) {
                int nr = wn * 32 + nf * 8 + g;
                b[nf][0] = __float_as_uint(Bb[nr * 20 + kb + tq]);
                b[nf][1] = __float_as_uint(Bb[nr * 20 + kb + tq + 4]);
            }
            #pragma unroll
            for (int mf = 0; mf < 2; mf++)
                #pragma unroll
                for (int nf = 0; nf < 4; nf++)
                    asm volatile(
                        "mma.sync.aligned.m16n8k8.row.col.f32.tf32.tf32.f32 "
                        "{%0,%1,%2,%3}, {%4,%5,%6,%7}, {%8,%9}, {%0,%1,%2,%3};"
                        : "+f"(acc[mf][nf][0]), "+f"(acc[mf][nf][1]),
                          "+f"(acc[mf][nf][2]), "+f"(acc[mf][nf][3])
                        : "r"(a[mf][0]), "r"(a[mf][1]), "r"(a[mf][2]), "r"(a[mf][3]),
                          "r"(b[nf][0]), "r"(b[nf][1]));
        }
    }
    // epilogue: scale by routing weight, scatter to original token rows
    #pragma unroll
    for (int mf = 0; mf < 2; mf++) {
        #pragma unroll
        for (int h = 0; h < 2; h++) {
            int m = wm * 32 + mf * 16 + g + h * 8;
            if (m < rem) {
                int s = g_perm[rowBase + m];
                if (s >= 0) {
                    float wv = g_wrow[rowBase + m];
                    #pragma unroll
                    for (int nf = 0; nf < 4; nf++) {
                        int n = d0 + wn * 32 + nf * 8 + tq * 2;
                        float2 v;
                        v.x = acc[mf][nf][h * 2 + 0] * wv;
                        v.y = acc[mf][nf][h * 2 + 1] * wv;
                        *(float2*)&out[(size_t)s * D + n] = v;
                    }
                }
            }
        }
    }
}

// ---------------- launch ----------------
extern "C" void kernel_launch(void* const* d_in, const int* in_sizes, int n_in,
                              void* d_out, int out_size) {
    const float* x     = (const float*)d_in[0];
    const int*   eidx  = (const int*)  d_in[1];
    const float* ew    = (const float*)d_in[2];
    const float* uA    = (const float*)d_in[3];
    const float* gA    = (const float*)d_in[4];
    const float* ulog  = (const float*)d_in[5];
    const float* glog  = (const float*)d_in[6];
    const float* down  = (const float*)d_in[7];
    const float* ubank = (const float*)d_in[8];
    const float* gbank = (const float*)d_in[9];
    float* out = (float*)d_out;

    k_route<<<1, 1024>>>(eidx, ew, ulog, glog);
    k_mixed<<<256, 256>>>(ubank, gbank);
    k_trans<<<dim3(PP / 32, R / 32, 2 * E), dim3(32, 8)>>>(uA, gA);
    k_tproj<<<dim3(NT, 4), 256>>>(x);
    k_adapt<<<dim3(NT, PP / 256), 256>>>();
    k_down<<<dim3(D / 64, 8, E), 256>>>(down, out);
}

// round 5
// speedup vs baseline: 1.4868x; 1.1868x over previous
#include <cuda_runtime.h>
#include <cuda_bf16.h>
#include <cstdint>

#define S    1024
#define D    1024
#define PP   2816
#define R    64
#define E    8
#define MM   16
#define SPAD 1152
#define NT   (SPAD/16)   // 72 sixteen-row tiles

// ---------------- device scratch (static, no runtime alloc) ----------------
__device__ float g_alpha[2][E][MM];          // softmax mixture weights (0=up,1=gate)
__device__ float g_up_mixed[E*D*R];          // [E][D][R]
__device__ float g_gate_mixed[E*D*R];
__device__ float g_aut[E*R*PP];              // transposed up adapters [E][R][P]
__device__ float g_agt[E*R*PP];              // transposed gate adapters
__device__ int   g_perm[SPAD];               // permuted row -> token (or -1 pad)
__device__ float g_wrow[SPAD];               // routing weight per permuted row
__device__ int   g_poff[E+1];                // padded expert offsets (mult of 16)
__device__ int   g_etile[NT];                // expert per 16-row tile (or -1)
__device__ float g_tpart[4*SPAD*2*R];        // split-K partials of t (up|gate)
__device__ float g_inter[SPAD*PP];           // silu(gate)*up, tf32-rounded fp32

// ---------------- K1: routing, permutation, alphas ----------------
__global__ __launch_bounds__(1024) void k_route(const int* __restrict__ eidx,
                                                const float* __restrict__ ew,
                                                const float* __restrict__ ulog,
                                                const float* __restrict__ glog) {
    __shared__ int wcnt[32][E];
    __shared__ int woff[32][E];
    __shared__ int poff_s[E+1];
    int t = threadIdx.x;
    int e = eidx[t];                      // K = 1
    int w = t >> 5, lane = t & 31;
    if (lane < E) wcnt[w][lane] = 0;
    __syncthreads();
    unsigned mask = __match_any_sync(0xffffffffu, e);
    int posw = __popc(mask & ((1u << lane) - 1u));
    if (posw == 0) wcnt[w][e] = __popc(mask);
    __syncthreads();
    if (t < 256) {                        // exclusive prefix over warps per expert
        int e2 = t >> 5, w2 = t & 31;
        int sacc = 0;
        for (int ww = 0; ww < w2; ww++) sacc += wcnt[ww][e2];
        woff[w2][e2] = sacc;
    }
    __syncthreads();
    if (t == 0) {
        int o = 0;
        for (int e2 = 0; e2 < E; e2++) {
            poff_s[e2] = o;
            int c = woff[31][e2] + wcnt[31][e2];
            o += (c + 15) & ~15;          // pad each expert to 16 rows
        }
        poff_s[E] = o;
        for (int i = 0; i <= E; i++) g_poff[i] = poff_s[i];
    }
    __syncthreads();
    for (int i = t; i < SPAD; i += 1024) { g_perm[i] = -1; g_wrow[i] = 0.f; }
    __syncthreads();
    int row = poff_s[e] + woff[w][e] + posw;
    g_perm[row] = t;
    g_wrow[row] = ew[t];
    if (t < NT) {
        int r0 = t * 16; int ee = -1;
        for (int e2 = 0; e2 < E; e2++)
            if (r0 >= poff_s[e2] && r0 < poff_s[e2+1]) ee = e2;
        g_etile[t] = ee;
    }
    if (t < 2 * E) {                      // softmax over M=16
        int which = t & 1, e2 = t >> 1;
        const float* L = (which ? glog : ulog) + e2 * MM;
        float mx = L[0];
        for (int m = 1; m < MM; m++) mx = fmaxf(mx, L[m]);
        float sum = 0.f, ex[MM];
        for (int m = 0; m < MM; m++) { ex[m] = __expf(L[m] - mx); sum += ex[m]; }
        float inv = 1.f / sum;
        for (int m = 0; m < MM; m++) g_alpha[which][e2][m] = ex[m] * inv;
    }
}

// ---------------- K2: mixed bases [E,D,R] = alpha @ bank ----------------
__global__ __launch_bounds__(256) void k_mixed(const float* __restrict__ ubank,
                                               const float* __restrict__ gbank) {
    __shared__ float al[2 * E * MM];      // 256 floats
    int t = threadIdx.x;
    al[t] = ((const float*)g_alpha)[t];
    __syncthreads();
    int r = t & 63, dl = t >> 6;
    int d = blockIdx.x * 4 + dl;
    float au[E], ag[E];
    #pragma unroll
    for (int e = 0; e < E; e++) { au[e] = 0.f; ag[e] = 0.f; }
    #pragma unroll
    for (int m = 0; m < MM; m++) {
        float bu = ubank[(m * D + d) * R + r];
        float bg = gbank[(m * D + d) * R + r];
        #pragma unroll
        for (int e = 0; e < E; e++) {
            au[e] += al[e * MM + m] * bu;
            ag[e] += al[E * MM + e * MM + m] * bg;
        }
    }
    #pragma unroll
    for (int e = 0; e < E; e++) {
        g_up_mixed  [(e * D + d) * R + r] = au[e];
        g_gate_mixed[(e * D + d) * R + r] = ag[e];
    }
}

// ---------------- K2b: transpose adapters [E,P,R] -> [E,R,P] ----------------
__global__ __launch_bounds__(256) void k_trans(const float* __restrict__ uA,
                                               const float* __restrict__ gA) {
    int e = blockIdx.z >> 1, which = blockIdx.z & 1;
    const float* src = which ? gA : uA;
    float* dst = which ? g_agt : g_aut;
    int p0 = blockIdx.x * 32, r0 = blockIdx.y * 32;
    __shared__ float sm[32][33];
    int tx = threadIdx.x, ty = threadIdx.y;
    for (int i = ty; i < 32; i += 8)
        sm[i][tx] = src[(e * PP + p0 + i) * R + r0 + tx];
    __syncthreads();
    for (int i = ty; i < 32; i += 8)
        dst[(e * R + r0 + i) * PP + p0 + tx] = sm[tx][i];
}

// ---------------- K3: t = X_gathered @ mixed (split-K=4, pipelined smem) ----------------
#define TCK 32
__global__ __launch_bounds__(256) void k_tproj(const float* __restrict__ x) {
    int tile = blockIdx.x;
    int e = g_etile[tile];
    if (e < 0) return;
    int split = blockIdx.y, d0 = split * 256;
    int base = tile * 16;
    __shared__ float xs[16][256];         // X tile, d-contiguous per row
    __shared__ float ms[3][TCK][128];     // mixed chunks: [d][col] col<64 up, >=64 gate
    __shared__ int ps[16];
    int t = threadIdx.x;
    if (t < 16) ps[t] = g_perm[base + t];
    __syncthreads();

    // X tile via cp.async (one group): 16 rows x 64 f4
    #pragma unroll
    for (int i = 0; i < 4; i++) {
        int q = t + i * 256;
        int row = q >> 6, c4 = q & 63;
        int s = ps[row];
        unsigned sa = (unsigned)__cvta_generic_to_shared(&xs[row][c4 * 4]);
        const float* src = &x[(size_t)(s < 0 ? 0 : s) * D + d0 + c4 * 4];
        int sz = (s >= 0) ? 16 : 0;
        asm volatile("cp.async.cg.shared.global [%0], [%1], 16, %2;"
                     :: "r"(sa), "l"(src), "r"(sz));
    }
    asm volatile("cp.async.commit_group;");

    const float* upb = g_up_mixed   + (size_t)(e * D + d0) * R;
    const float* gtb = g_gate_mixed + (size_t)(e * D + d0) * R;
    auto load_ms = [&](int ck, int buf) {
        #pragma unroll
        for (int i = 0; i < 4; i++) {
            int q = t + i * 256;          // 1024 f4 slots = 32 d x 32 f4
            int d = q >> 5, c = q & 31;   // c<16: up r-slot, c>=16: gate r-slot
            const float* src = (c < 16)
                ? upb + (size_t)(ck * TCK + d) * R + c * 4
                : gtb + (size_t)(ck * TCK + d) * R + (c - 16) * 4;
            unsigned sa = (unsigned)__cvta_generic_to_shared(&ms[buf][d][c * 4]);
            asm volatile("cp.async.cg.shared.global [%0], [%1], 16, 16;"
                         :: "r"(sa), "l"(src));
        }
        asm volatile("cp.async.commit_group;");
    };

    load_ms(0, 0);
    load_ms(1, 1);

    int col = t & 127, rg = t >> 7;       // col: 0-63 up, 64-127 gate; rg: row group
    float acc[8] = {};
    const int NCK = 256 / TCK;            // 8 chunks

    for (int ck = 0; ck < NCK; ck++) {
        if (ck + 2 < NCK) { asm volatile("cp.async.wait_group 1;"); }
        else              { asm volatile("cp.async.wait_group 0;"); }
        __syncthreads();
        if (ck + 2 < NCK) load_ms(ck + 2, (ck + 2) % 3);
        const float (*mb)[128] = ms[ck % 3];
        #pragma unroll
        for (int dd = 0; dd < TCK; dd += 4) {
            float4 xv[8];
            #pragma unroll
            for (int i = 0; i < 8; i++)
                xv[i] = *(const float4*)&xs[rg * 8 + i][ck * TCK + dd];
            #pragma unroll
            for (int j = 0; j < 4; j++) {
                float m = mb[dd + j][col];
                #pragma unroll
                for (int i = 0; i < 8; i++)
                    acc[i] += ((const float*)&xv[i])[j] * m;
            }
        }
        __syncthreads();
    }
    #pragma unroll
    for (int i = 0; i < 8; i++)
        g_tpart[(size_t)(split * SPAD + base + rg * 8 + i) * 128 + col] = acc[i];
}

// ---------------- K4: expert-persistent adapters + silu, tf32-rounded inter ----
// grid (PP/128, E); adapters for (e, 128-col p-block) cached in smem once.
// dyn smem: au[64][128] | ag[64][128] | ts[16][128]  = 73728 B
__global__ __launch_bounds__(256) void k_adapt() {
    extern __shared__ float sm4[];
    float* sau = sm4;                     // [64][128]
    float* sag = sm4 + 64 * 128;          // [64][128]
    float* ts  = sm4 + 2 * 64 * 128;      // [16][128]
    int e = blockIdx.y;
    int p0 = blockIdx.x * 128;
    int t = threadIdx.x;
    int r0 = g_poff[e], r1 = g_poff[e + 1];
    int ntiles = (r1 - r0) >> 4;
    if (ntiles <= 0) return;

    // stage adapters once: 2048 f4 per matrix
    const float* aup = g_aut + (size_t)e * R * PP + p0;
    const float* agp = g_agt + (size_t)e * R * PP + p0;
    #pragma unroll
    for (int i = 0; i < 8; i++) {
        int q = t + i * 256;              // over 2048 f4
        int r = q >> 5, c4 = q & 31;
        unsigned sa = (unsigned)__cvta_generic_to_shared(&sau[r * 128 + c4 * 4]);
        asm volatile("cp.async.cg.shared.global [%0], [%1], 16, 16;"
                     :: "r"(sa), "l"(aup + (size_t)r * PP + c4 * 4));
        unsigned sg = (unsigned)__cvta_generic_to_shared(&sag[r * 128 + c4 * 4]);
        asm volatile("cp.async.cg.shared.global [%0], [%1], 16, 16;"
                     :: "r"(sg), "l"(agp + (size_t)r * PP + c4 * 4));
    }
    asm volatile("cp.async.commit_group;");
    asm volatile("cp.async.wait_group 0;");
    __syncthreads();

    int c = t & 31, rg = t >> 5;          // c: 4 cols each; rg: warp -> 2 rows
    for (int tl = 0; tl < ntiles; tl++) {
        int base = r0 + tl * 16;
        __syncthreads();                  // ts write-after-read fence
        // reduce 4 split-K partials into ts (512 f4 / 256 thr = 2 each)
        #pragma unroll
        for (int i = 0; i < 2; i++) {
            int q = t + i * 256;
            int row = q >> 5, c4 = q & 31;
            float4 acc = make_float4(0.f, 0.f, 0.f, 0.f);
            #pragma unroll
            for (int sp = 0; sp < 4; sp++) {
                float4 v = *(const float4*)&g_tpart[(size_t)(sp * SPAD + base + row) * 128 + c4 * 4];
                acc.x += v.x; acc.y += v.y; acc.z += v.z; acc.w += v.w;
            }
            *(float4*)&ts[row * 128 + c4 * 4] = acc;
        }
        __syncthreads();

        float accu[2][4] = {}, accg[2][4] = {};
        #pragma unroll 4
        for (int r = 0; r < R; r++) {
            float4 au  = *(const float4*)&sau[r * 128 + c * 4];
            float4 ag4 = *(const float4*)&sag[r * 128 + c * 4];
            #pragma unroll
            for (int i = 0; i < 2; i++) {
                float tu  = ts[(rg * 2 + i) * 128 + r];
                float tg2 = ts[(rg * 2 + i) * 128 + 64 + r];
                accu[i][0] += tu * au.x;  accu[i][1] += tu * au.y;
                accu[i][2] += tu * au.z;  accu[i][3] += tu * au.w;
                accg[i][0] += tg2 * ag4.x; accg[i][1] += tg2 * ag4.y;
                accg[i][2] += tg2 * ag4.z; accg[i][3] += tg2 * ag4.w;
            }
        }
        #pragma unroll
        for (int i = 0; i < 2; i++) {
            int row = base + rg * 2 + i;
            float4 o;
            #pragma unroll
            for (int cc = 0; cc < 4; cc++) {
                float gv = accg[i][cc], uv = accu[i][cc];
                float sv = uv * gv / (1.f + __expf(-gv));   // up * silu(gate)
                unsigned b; asm("cvt.rna.tf32.f32 %0, %1;" : "=r"(b) : "f"(sv));
                ((float*)&o)[cc] = __uint_as_float(b);
            }
            *(float4*)&g_inter[(size_t)row * PP + p0 + c * 4] = o;
        }
    }
}

// ---------------- K5: routed down GEMM, 256xK x 64 tiles, tf32 mma ----------------
// grid (16 n-tiles, E). One 256-row M tile covers an expert (loop for safety).
// dyn smem: As[3][256*20] | Bs[3][64*20] = 76800 B
#define TK 16
__global__ __launch_bounds__(256) void k_down(const float* __restrict__ down,
                                              float* __restrict__ out) {
    extern __shared__ float sm5[];
    float* As = sm5;                      // 3 stages of 256*20
    float* Bs = sm5 + 3 * 256 * 20;       // 3 stages of 64*20
    int e = blockIdx.y;
    int r0 = g_poff[e], r1 = g_poff[e + 1];
    int d0 = blockIdx.x * 64;
    const float* Bg = down + ((size_t)e * D + d0) * PP;
    int t = threadIdx.x;
    int lane = t & 31, g = lane >> 2, tq = lane & 3;
    int w = t >> 5;
    const int NKT = PP / TK;              // 176

    for (int rowBase = r0; rowBase < r1; rowBase += 256) {
        int rem = min(256, r1 - rowBase);
        const float* Ag = g_inter + (size_t)rowBase * PP;

        auto issue = [&](int kt, int buf) {
            int kk = kt * TK;
            #pragma unroll
            for (int i = 0; i < 4; i++) {
                int idx = t + i * 256;
                int row = idx >> 2, c4 = idx & 3;
                const float* src = Ag + (size_t)row * PP + kk + c4 * 4;
                bool ok = row < rem;
                unsigned sa = (unsigned)__cvta_generic_to_shared(&As[buf * 256 * 20 + row * 20 + c4 * 4]);
                int sz = ok ? 16 : 0;
                asm volatile("cp.async.cg.shared.global [%0], [%1], 16, %2;"
                             :: "r"(sa), "l"(ok ? src : Ag), "r"(sz));
            }
            {
                int row = t >> 2, c4 = t & 3;
                const float* src = Bg + (size_t)row * PP + kk + c4 * 4;
                unsigned sa = (unsigned)__cvta_generic_to_shared(&Bs[buf * 64 * 20 + row * 20 + c4 * 4]);
                asm volatile("cp.async.cg.shared.global [%0], [%1], 16, 16;"
                             :: "r"(sa), "l"(src));
            }
            asm volatile("cp.async.commit_group;");
        };

        issue(0, 0); issue(1, 1);
        float acc[2][8][4] = {};

        for (int kt = 0; kt < NKT; kt++) {
            if (kt + 2 < NKT) { asm volatile("cp.async.wait_group 1;"); }
            else              { asm volatile("cp.async.wait_group 0;"); }
            __syncthreads();
            if (kt + 2 < NKT) issue(kt + 2, (kt + 2) % 3);
            const float* Ab = As + (kt % 3) * 256 * 20;
            const float* Bb = Bs + (kt % 3) * 64 * 20;
            #pragma unroll
            for (int ks = 0; ks < 2; ks++) {
                int kb = ks * 8;
                unsigned a[2][4], b[8][2];
                #pragma unroll
                for (int mf = 0; mf < 2; mf++) {
                    int mr = w * 32 + mf * 16 + g;
                    a[mf][0] = __float_as_uint(Ab[ mr      * 20 + kb + tq]);
                    a[mf][1] = __float_as_uint(Ab[(mr + 8) * 20 + kb + tq]);
                    a[mf][2] = __float_as_uint(Ab[ mr      * 20 + kb + tq + 4]);
                    a[mf][3] = __float_as_uint(Ab[(mr + 8) * 20 + kb + tq + 4]);
                }
                #pragma unroll
                for (int nf = 0; nf < 8; nf++) {
                    int nr = nf * 8 + g;
                    b[nf][0] = __float_as_uint(Bb[nr * 20 + kb + tq]);
                    b[nf][1] = __float_as_uint(Bb[nr * 20 + kb + tq + 4]);
                }
                #pragma unroll
                for (int mf = 0; mf < 2; mf++)
                    #pragma unroll
                    for (int nf = 0; nf < 8; nf++)
                        asm volatile(
                            "mma.sync.aligned.m16n8k8.row.col.f32.tf32.tf32.f32 "
                            "{%0,%1,%2,%3}, {%4,%5,%6,%7}, {%8,%9}, {%0,%1,%2,%3};"
                            : "+f"(acc[mf][nf][0]), "+f"(acc[mf][nf][1]),
                              "+f"(acc[mf][nf][2]), "+f"(acc[mf][nf][3])
                            : "r"(a[mf][0]), "r"(a[mf][1]), "r"(a[mf][2]), "r"(a[mf][3]),
                              "r"(b[nf][0]), "r"(b[nf][1]));
            }
        }
        // epilogue: scale by routing weight, scatter to original token rows
        #pragma unroll
        for (int mf = 0; mf < 2; mf++) {
            #pragma unroll
            for (int h = 0; h < 2; h++) {
                int m = w * 32 + mf * 16 + g + h * 8;
                if (m < rem) {
                    int s = g_perm[rowBase + m];
                    if (s >= 0) {
                        float wv = g_wrow[rowBase + m];
                        #pragma unroll
                        for (int nf = 0; nf < 8; nf++) {
                            int n = d0 + nf * 8 + tq * 2;
                            float2 v;
                            v.x = acc[mf][nf][h * 2 + 0] * wv;
                            v.y = acc[mf][nf][h * 2 + 1] * wv;
                            *(float2*)&out[(size_t)s * D + n] = v;
                        }
                    }
                }
            }
        }
        __syncthreads();                  // reuse smem next rowBase iter
    }
}

// ---------------- launch ----------------
extern "C" void kernel_launch(void* const* d_in, const int* in_sizes, int n_in,
                              void* d_out, int out_size) {
    const float* x     = (const float*)d_in[0];
    const int*   eidx  = (const int*)  d_in[1];
    const float* ew    = (const float*)d_in[2];
    const float* uA    = (const float*)d_in[3];
    const float* gA    = (const float*)d_in[4];
    const float* ulog  = (const float*)d_in[5];
    const float* glog  = (const float*)d_in[6];
    const float* down  = (const float*)d_in[7];
    const float* ubank = (const float*)d_in[8];
    const float* gbank = (const float*)d_in[9];
    float* out = (float*)d_out;

    const int ADAPT_SMEM = (2 * 64 * 128 + 16 * 128) * 4;   // 73728
    const int DOWN_SMEM  = (3 * 256 * 20 + 3 * 64 * 20) * 4; // 76800
    cudaFuncSetAttribute(k_adapt, cudaFuncAttributeMaxDynamicSharedMemorySize, ADAPT_SMEM);
    cudaFuncSetAttribute(k_down,  cudaFuncAttributeMaxDynamicSharedMemorySize, DOWN_SMEM);

    k_route<<<1, 1024>>>(eidx, ew, ulog, glog);
    k_mixed<<<256, 256>>>(ubank, gbank);
    k_trans<<<dim3(PP / 32, R / 32, 2 * E), dim3(32, 8)>>>(uA, gA);
    k_tproj<<<dim3(NT, 4), 256>>>(x);
    k_adapt<<<dim3(PP / 128, E), 256, ADAPT_SMEM>>>();
    k_down<<<dim3(D / 64, E), 256, DOWN_SMEM>>>(down, out);
}

// round 9
// speedup vs baseline: 1.6086x; 1.0819x over previous
#include <cuda_runtime.h>
#include <cuda_bf16.h>
#include <cstdint>

#define S    1024
#define D    1024
#define PP   2816
#define R    64
#define E    8
#define MM   16
#define SPAD 1152
#define NT   (SPAD/16)   // 72 sixteen-row tiles

// ---------------- device scratch (static, no runtime alloc) ----------------
__device__ float g_alpha[2][E][MM];          // softmax mixture weights (0=up,1=gate)
__device__ float g_up_mixed[E*D*R];          // [E][D][R]
__device__ float g_gate_mixed[E*D*R];
__device__ float g_aut[E*R*PP];              // transposed up adapters [E][R][P]
__device__ float g_agt[E*R*PP];              // transposed gate adapters
__device__ int   g_perm[SPAD];               // permuted row -> token (or -1 pad)
__device__ float g_wrow[SPAD];               // routing weight per permuted row
__device__ int   g_poff[E+1];                // padded expert offsets (mult of 16)
__device__ int   g_etile[NT];                // expert per 16-row tile (or -1)
__device__ float g_tpart[4*SPAD*2*R + 64*128]; // split-K partials (+pad for 32-row windows)
__device__ float g_inter[SPAD*PP];           // silu(gate)*up, tf32-rounded fp32

// ---------------- K1: routing, permutation, alphas ----------------
__global__ __launch_bounds__(1024) void k_route(const int* __restrict__ eidx,
                                                const float* __restrict__ ew,
                                                const float* __restrict__ ulog,
                                                const float* __restrict__ glog) {
    __shared__ int wcnt[32][E];
    __shared__ int woff[32][E];
    __shared__ int poff_s[E+1];
    int t = threadIdx.x;
    int e = eidx[t];                      // K = 1
    int w = t >> 5, lane = t & 31;
    if (lane < E) wcnt[w][lane] = 0;
    __syncthreads();
    unsigned mask = __match_any_sync(0xffffffffu, e);
    int posw = __popc(mask & ((1u << lane) - 1u));
    if (posw == 0) wcnt[w][e] = __popc(mask);
    __syncthreads();
    if (t < 256) {                        // exclusive prefix over warps per expert
        int e2 = t >> 5, w2 = t & 31;
        int sacc = 0;
        for (int ww = 0; ww < w2; ww++) sacc += wcnt[ww][e2];
        woff[w2][e2] = sacc;
    }
    __syncthreads();
    if (t == 0) {
        int o = 0;
        for (int e2 = 0; e2 < E; e2++) {
            poff_s[e2] = o;
            int c = woff[31][e2] + wcnt[31][e2];
            o += (c + 15) & ~15;          // pad each expert to 16 rows
        }
        poff_s[E] = o;
        for (int i = 0; i <= E; i++) g_poff[i] = poff_s[i];
    }
    __syncthreads();
    for (int i = t; i < SPAD; i += 1024) { g_perm[i] = -1; g_wrow[i] = 0.f; }
    __syncthreads();
    int row = poff_s[e] + woff[w][e] + posw;
    g_perm[row] = t;
    g_wrow[row] = ew[t];
    if (t < NT) {
        int r0 = t * 16; int ee = -1;
        for (int e2 = 0; e2 < E; e2++)
            if (r0 >= poff_s[e2] && r0 < poff_s[e2+1]) ee = e2;
        g_etile[t] = ee;
    }
    if (t < 2 * E) {                      // softmax over M=16
        int which = t & 1, e2 = t >> 1;
        const float* L = (which ? glog : ulog) + e2 * MM;
        float mx = L[0];
        for (int m = 1; m < MM; m++) mx = fmaxf(mx, L[m]);
        float sum = 0.f, ex[MM];
        for (int m = 0; m < MM; m++) { ex[m] = __expf(L[m] - mx); sum += ex[m]; }
        float inv = 1.f / sum;
        for (int m = 0; m < MM; m++) g_alpha[which][e2][m] = ex[m] * inv;
    }
}

// ---------------- K2: mixed bases [E,D,R] = alpha @ bank ----------------
__global__ __launch_bounds__(256) void k_mixed(const float* __restrict__ ubank,
                                               const float* __restrict__ gbank) {
    __shared__ float al[2 * E * MM];      // 256 floats
    int t = threadIdx.x;
    al[t] = ((const float*)g_alpha)[t];
    __syncthreads();
    int r = t & 63, dl = t >> 6;
    int d = blockIdx.x * 4 + dl;
    float au[E], ag[E];
    #pragma unroll
    for (int e = 0; e < E; e++) { au[e] = 0.f; ag[e] = 0.f; }
    #pragma unroll
    for (int m = 0; m < MM; m++) {
        float bu = ubank[(m * D + d) * R + r];
        float bg = gbank[(m * D + d) * R + r];
        #pragma unroll
        for (int e = 0; e < E; e++) {
            au[e] += al[e * MM + m] * bu;
            ag[e] += al[E * MM + e * MM + m] * bg;
        }
    }
    #pragma unroll
    for (int e = 0; e < E; e++) {
        g_up_mixed  [(e * D + d) * R + r] = au[e];
        g_gate_mixed[(e * D + d) * R + r] = ag[e];
    }
}

// ---------------- K2b: transpose adapters [E,P,R] -> [E,R,P] ----------------
__global__ __launch_bounds__(256) void k_trans(const float* __restrict__ uA,
                                               const float* __restrict__ gA) {
    int e = blockIdx.z >> 1, which = blockIdx.z & 1;
    const float* src = which ? gA : uA;
    float* dst = which ? g_agt : g_aut;
    int p0 = blockIdx.x * 32, r0 = blockIdx.y * 32;
    __shared__ float sm[32][33];
    int tx = threadIdx.x, ty = threadIdx.y;
    for (int i = ty; i < 32; i += 8)
        sm[i][tx] = src[(e * PP + p0 + i) * R + r0 + tx];
    __syncthreads();
    for (int i = ty; i < 32; i += 8)
        dst[(e * R + r0 + i) * PP + p0 + tx] = sm[tx][i];
}

// ---------------- K3: t = X_gathered @ mixed (split-K=4, pipelined smem) ----------------
#define TCK 32
__global__ __launch_bounds__(256) void k_tproj(const float* __restrict__ x) {
    int tile = blockIdx.x;
    int e = g_etile[tile];
    if (e < 0) return;
    int split = blockIdx.y, d0 = split * 256;
    int base = tile * 16;
    __shared__ float xs[16][256];         // X tile, d-contiguous per row
    __shared__ float ms[3][TCK][128];     // mixed chunks: [d][col] col<64 up, >=64 gate
    __shared__ int ps[16];
    int t = threadIdx.x;
    if (t < 16) ps[t] = g_perm[base + t];
    __syncthreads();

    // X tile via cp.async (one group): 16 rows x 64 f4
    #pragma unroll
    for (int i = 0; i < 4; i++) {
        int q = t + i * 256;
        int row = q >> 6, c4 = q & 63;
        int s = ps[row];
        unsigned sa = (unsigned)__cvta_generic_to_shared(&xs[row][c4 * 4]);
        const float* src = &x[(size_t)(s < 0 ? 0 : s) * D + d0 + c4 * 4];
        int sz = (s >= 0) ? 16 : 0;
        asm volatile("cp.async.cg.shared.global [%0], [%1], 16, %2;"
                     :: "r"(sa), "l"(src), "r"(sz));
    }
    asm volatile("cp.async.commit_group;");

    const float* upb = g_up_mixed   + (size_t)(e * D + d0) * R;
    const float* gtb = g_gate_mixed + (size_t)(e * D + d0) * R;
    auto load_ms = [&](int ck, int buf) {
        #pragma unroll
        for (int i = 0; i < 4; i++) {
            int q = t + i * 256;          // 1024 f4 slots = 32 d x 32 f4
            int d = q >> 5, c = q & 31;   // c<16: up r-slot, c>=16: gate r-slot
            const float* src = (c < 16)
                ? upb + (size_t)(ck * TCK + d) * R + c * 4
                : gtb + (size_t)(ck * TCK + d) * R + (c - 16) * 4;
            unsigned sa = (unsigned)__cvta_generic_to_shared(&ms[buf][d][c * 4]);
            asm volatile("cp.async.cg.shared.global [%0], [%1], 16, 16;"
                         :: "r"(sa), "l"(src));
        }
        asm volatile("cp.async.commit_group;");
    };

    load_ms(0, 0);
    load_ms(1, 1);

    int col = t & 127, rg = t >> 7;       // col: 0-63 up, 64-127 gate; rg: row group
    float acc[8] = {};
    const int NCK = 256 / TCK;            // 8 chunks

    for (int ck = 0; ck < NCK; ck++) {
        if (ck + 2 < NCK) { asm volatile("cp.async.wait_group 1;"); }
        else              { asm volatile("cp.async.wait_group 0;"); }
        __syncthreads();
        if (ck + 2 < NCK) load_ms(ck + 2, (ck + 2) % 3);
        const float (*mb)[128] = ms[ck % 3];
        #pragma unroll
        for (int dd = 0; dd < TCK; dd += 4) {
            float4 xv[8];
            #pragma unroll
            for (int i = 0; i < 8; i++)
                xv[i] = *(const float4*)&xs[rg * 8 + i][ck * TCK + dd];
            #pragma unroll
            for (int j = 0; j < 4; j++) {
                float m = mb[dd + j][col];
                #pragma unroll
                for (int i = 0; i < 8; i++)
                    acc[i] += ((const float*)&xv[i])[j] * m;
            }
        }
        __syncthreads();
    }
    #pragma unroll
    for (int i = 0; i < 8; i++)
        g_tpart[(size_t)(split * SPAD + base + rg * 8 + i) * 128 + col] = acc[i];
}

// ---------------- K4: expert-persistent adapters + silu, 32 rows/iter ----------
// dyn smem: au[64][128] | ag[64][128] | ts[32][128]  = 81920 B
__global__ __launch_bounds__(256) void k_adapt() {
    extern __shared__ float sm4[];
    float* sau = sm4;                     // [64][128]
    float* sag = sm4 + 64 * 128;          // [64][128]
    float* ts  = sm4 + 2 * 64 * 128;      // [32][128]
    int e = blockIdx.y;
    int p0 = blockIdx.x * 128;
    int t = threadIdx.x;
    int r0 = g_poff[e], r1 = g_poff[e + 1];
    if (r1 <= r0) return;

    const float* aup = g_aut + (size_t)e * R * PP + p0;
    const float* agp = g_agt + (size_t)e * R * PP + p0;
    #pragma unroll
    for (int i = 0; i < 8; i++) {
        int q = t + i * 256;              // over 2048 f4
        int r = q >> 5, c4 = q & 31;
        unsigned sa = (unsigned)__cvta_generic_to_shared(&sau[r * 128 + c4 * 4]);
        asm volatile("cp.async.cg.shared.global [%0], [%1], 16, 16;"
                     :: "r"(sa), "l"(aup + (size_t)r * PP + c4 * 4));
        unsigned sg = (unsigned)__cvta_generic_to_shared(&sag[r * 128 + c4 * 4]);
        asm volatile("cp.async.cg.shared.global [%0], [%1], 16, 16;"
                     :: "r"(sg), "l"(agp + (size_t)r * PP + c4 * 4));
    }
    asm volatile("cp.async.commit_group;");
    asm volatile("cp.async.wait_group 0;");
    __syncthreads();

    int c = t & 31, rg = t >> 5;          // c: 4 cols each; rg: warp -> 4 rows
    for (int base = r0; base < r1; base += 32) {
        __syncthreads();                  // ts write-after-read fence
        // reduce 4 split-K partials into ts (1024 f4 / 256 thr = 4 each)
        #pragma unroll
        for (int i = 0; i < 4; i++) {
            int q = t + i * 256;
            int row = q >> 5, c4 = q & 31;
            float4 acc = make_float4(0.f, 0.f, 0.f, 0.f);
            #pragma unroll
            for (int sp = 0; sp < 4; sp++) {
                float4 v = *(const float4*)&g_tpart[(size_t)(sp * SPAD + base + row) * 128 + c4 * 4];
                acc.x += v.x; acc.y += v.y; acc.z += v.z; acc.w += v.w;
            }
            *(float4*)&ts[row * 128 + c4 * 4] = acc;
        }
        __syncthreads();

        float accu[4][4] = {}, accg[4][4] = {};
        #pragma unroll 4
        for (int r = 0; r < R; r++) {
            float4 au  = *(const float4*)&sau[r * 128 + c * 4];
            float4 ag4 = *(const float4*)&sag[r * 128 + c * 4];
            #pragma unroll
            for (int i = 0; i < 4; i++) {
                float tu  = ts[(rg * 4 + i) * 128 + r];
                float tg2 = ts[(rg * 4 + i) * 128 + 64 + r];
                accu[i][0] += tu * au.x;  accu[i][1] += tu * au.y;
                accu[i][2] += tu * au.z;  accu[i][3] += tu * au.w;
                accg[i][0] += tg2 * ag4.x; accg[i][1] += tg2 * ag4.y;
                accg[i][2] += tg2 * ag4.z; accg[i][3] += tg2 * ag4.w;
            }
        }
        #pragma unroll
        for (int i = 0; i < 4; i++) {
            int row = base + rg * 4 + i;
            if (row < r1) {
                float4 o;
                #pragma unroll
                for (int cc = 0; cc < 4; cc++) {
                    float gv = accg[i][cc], uv = accu[i][cc];
                    float sv = uv * gv / (1.f + __expf(-gv));   // up * silu(gate)
                    unsigned b; asm("cvt.rna.tf32.f32 %0, %1;" : "=r"(b) : "f"(sv));
                    ((float*)&o)[cc] = __uint_as_float(b);
                }
                *(float4*)&g_inter[(size_t)row * PP + p0 + c * 4] = o;
            }
        }
    }
}

// ---------------- K5: routed down GEMM, 256xK x 64 tiles, tf32 mma, 512 thr ----
// grid (16 n-tiles, E). dyn smem: As[3][256*20] | Bs[3][64*20] = 76800 B
#define TK 16
__global__ __launch_bounds__(512) void k_down(const float* __restrict__ down,
                                              float* __restrict__ out) {
    extern __shared__ float sm5[];
    float* As = sm5;                      // 3 stages of 256*20
    float* Bs = sm5 + 3 * 256 * 20;       // 3 stages of 64*20
    int e = blockIdx.y;
    int r0 = g_poff[e], r1 = g_poff[e + 1];
    int d0 = blockIdx.x * 64;
    const float* Bg = down + ((size_t)e * D + d0) * PP;
    int t = threadIdx.x;
    int lane = t & 31, g = lane >> 2, tq = lane & 3;
    int w = t >> 5, wm = w & 7, wn = w >> 3;   // 8 m-groups x 2 n-groups
    const int NKT = PP / TK;              // 176

    for (int rowBase = r0; rowBase < r1; rowBase += 256) {
        int rem = min(256, r1 - rowBase);
        const float* Ag = g_inter + (size_t)rowBase * PP;

        auto issue = [&](int kt, int buf) {
            int kk = kt * TK;
            #pragma unroll
            for (int i = 0; i < 2; i++) {
                int idx = t + i * 512;            // 1024 f4 over A (256 rows x 4 f4)
                int row = idx >> 2, c4 = idx & 3;
                const float* src = Ag + (size_t)row * PP + kk + c4 * 4;
                bool ok = row < rem;
                unsigned sa = (unsigned)__cvta_generic_to_shared(&As[buf * 256 * 20 + row * 20 + c4 * 4]);
                int sz = ok ? 16 : 0;
                asm volatile("cp.async.cg.shared.global [%0], [%1], 16, %2;"
                             :: "r"(sa), "l"(ok ? src : Ag), "r"(sz));
            }
            if (t < 256) {                        // 256 f4 over B (64 rows x 4 f4)
                int row = t >> 2, c4 = t & 3;
                const float* src = Bg + (size_t)row * PP + kk + c4 * 4;
                unsigned sa = (unsigned)__cvta_generic_to_shared(&Bs[buf * 64 * 20 + row * 20 + c4 * 4]);
                asm volatile("cp.async.cg.shared.global [%0], [%1], 16, 16;"
                             :: "r"(sa), "l"(src));
            }
            asm volatile("cp.async.commit_group;");
        };

        issue(0, 0); issue(1, 1);
        float acc[2][4][4] = {};

        for (int kt = 0; kt < NKT; kt++) {
            if (kt + 2 < NKT) { asm volatile("cp.async.wait_group 1;"); }
            else              { asm volatile("cp.async.wait_group 0;"); }
            __syncthreads();
            if (kt + 2 < NKT) issue(kt + 2, (kt + 2) % 3);
            const float* Ab = As + (kt % 3) * 256 * 20;
            const float* Bb = Bs + (kt % 3) * 64 * 20;
            #pragma unroll
            for (int ks = 0; ks < 2; ks++) {
                int kb = ks * 8;
                unsigned a[2][4], b[4][2];
                #pragma unroll
                for (int mf = 0; mf < 2; mf++) {
                    int mr = wm * 32 + mf * 16 + g;
                    a[mf][0] = __float_as_uint(Ab[ mr      * 20 + kb + tq]);
                    a[mf][1] = __float_as_uint(Ab[(mr + 8) * 20 + kb + tq]);
                    a[mf][2] = __float_as_uint(Ab[ mr      * 20 + kb + tq + 4]);
                    a[mf][3] = __float_as_uint(Ab[(mr + 8) * 20 + kb + tq + 4]);
                }
                #pragma unroll
                for (int nf = 0; nf < 4; nf++) {
                    int nr = wn * 32 + nf * 8 + g;
                    b[nf][0] = __float_as_uint(Bb[nr * 20 + kb + tq]);
                    b[nf][1] = __float_as_uint(Bb[nr * 20 + kb + tq + 4]);
                }
                #pragma unroll
                for (int mf = 0; mf < 2; mf++)
                    #pragma unroll
                    for (int nf = 0; nf < 4; nf++)
                        asm volatile(
                            "mma.sync.aligned.m16n8k8.row.col.f32.tf32.tf32.f32 "
                            "{%0,%1,%2,%3}, {%4,%5,%6,%7}, {%8,%9}, {%0,%1,%2,%3};"
                            : "+f"(acc[mf][nf][0]), "+f"(acc[mf][nf][1]),
                              "+f"(acc[mf][nf][2]), "+f"(acc[mf][nf][3])
                            : "r"(a[mf][0]), "r"(a[mf][1]), "r"(a[mf][2]), "r"(a[mf][3]),
                              "r"(b[nf][0]), "r"(b[nf][1]));
            }
        }
        // epilogue: scale by routing weight, scatter to original token rows
        #pragma unroll
        for (int mf = 0; mf < 2; mf++) {
            #pragma unroll
            for (int h = 0; h < 2; h++) {
                int m = wm * 32 + mf * 16 + g + h * 8;
                if (m < rem) {
                    int s = g_perm[rowBase + m];
                    if (s >= 0) {
                        float wv = g_wrow[rowBase + m];
                        #pragma unroll
                        for (int nf = 0; nf < 4; nf++) {
                            int n = d0 + wn * 32 + nf * 8 + tq * 2;
                            float2 v;
                            v.x = acc[mf][nf][h * 2 + 0] * wv;
                            v.y = acc[mf][nf][h * 2 + 1] * wv;
                            *(float2*)&out[(size_t)s * D + n] = v;
                        }
                    }
                }
            }
        }
        __syncthreads();                  // reuse smem next rowBase iter
    }
}

// ---------------- launch ----------------
extern "C" void kernel_launch(void* const* d_in, const int* in_sizes, int n_in,
                              void* d_out, int out_size) {
    const float* x     = (const float*)d_in[0];
    const int*   eidx  = (const int*)  d_in[1];
    const float* ew    = (const float*)d_in[2];
    const float* uA    = (const float*)d_in[3];
    const float* gA    = (const float*)d_in[4];
    const float* ulog  = (const float*)d_in[5];
    const float* glog  = (const float*)d_in[6];
    const float* down  = (const float*)d_in[7];
    const float* ubank = (const float*)d_in[8];
    const float* gbank = (const float*)d_in[9];
    float* out = (float*)d_out;

    const int ADAPT_SMEM = (2 * 64 * 128 + 32 * 128) * 4;    // 81920
    const int DOWN_SMEM  = (3 * 256 * 20 + 3 * 64 * 20) * 4; // 76800
    cudaFuncSetAttribute(k_adapt, cudaFuncAttributeMaxDynamicSharedMemorySize, ADAPT_SMEM);
    cudaFuncSetAttribute(k_down,  cudaFuncAttributeMaxDynamicSharedMemorySize, DOWN_SMEM);

    k_route<<<1, 1024>>>(eidx, ew, ulog, glog);
    k_mixed<<<256, 256>>>(ubank, gbank);
    k_trans<<<dim3(PP / 32, R / 32, 2 * E), dim3(32, 8)>>>(uA, gA);
    k_tproj<<<dim3(NT, 4), 256>>>(x);
    k_adapt<<<dim3(PP / 128, E), 256, ADAPT_SMEM>>>();
    k_down<<<dim3(D / 64, E), 512, DOWN_SMEM>>>(down, out);
}

// round 11
// speedup vs baseline: 1.9219x; 1.1948x over previous
#include <cuda_runtime.h>
#include <cuda_fp16.h>
#include <cstdint>

#define S    1024
#define D    1024
#define PP   2816
#define R    64
#define E    8
#define MM   16
#define SPAD 1152
#define NT   (SPAD/16)   // 72 sixteen-row tiles

// ---------------- device scratch (static, no runtime alloc) ----------------
__device__ float g_alpha[2][E][MM];          // softmax mixture weights (0=up,1=gate)
__device__ float g_up_mixed[E*D*R];          // [E][D][R]
__device__ float g_gate_mixed[E*D*R];
__device__ float g_aut[E*R*PP];              // transposed up adapters [E][R][P]
__device__ float g_agt[E*R*PP];              // transposed gate adapters
__device__ int   g_perm[SPAD];               // permuted row -> token (or -1 pad)
__device__ float g_wrow[SPAD];               // routing weight per permuted row
__device__ int   g_poff[E+1];                // padded expert offsets (mult of 16)
__device__ int   g_etile[NT];                // expert per 16-row tile (or -1)
__device__ float g_tpart[4*SPAD*2*R + 64*128]; // split-K partials (+pad for 32-row windows)
__device__ __half g_inter[SPAD*PP];          // silu(gate)*up, fp16

__device__ __forceinline__ uint32_t s2u(const void* p) {
    uint32_t a;
    asm("{ .reg .u64 t; cvta.to.shared.u64 t, %1; cvt.u32.u64 %0, t; }" : "=r"(a) : "l"(p));
    return a;
}

// ---------------- K1: routing, permutation, alphas ----------------
__global__ __launch_bounds__(1024) void k_route(const int* __restrict__ eidx,
                                                const float* __restrict__ ew,
                                                const float* __restrict__ ulog,
                                                const float* __restrict__ glog) {
    __shared__ int wcnt[32][E];
    __shared__ int woff[32][E];
    __shared__ int poff_s[E+1];
    int t = threadIdx.x;
    int e = eidx[t];                      // K = 1
    int w = t >> 5, lane = t & 31;
    if (lane < E) wcnt[w][lane] = 0;
    __syncthreads();
    unsigned mask = __match_any_sync(0xffffffffu, e);
    int posw = __popc(mask & ((1u << lane) - 1u));
    if (posw == 0) wcnt[w][e] = __popc(mask);
    __syncthreads();
    if (t < 256) {                        // exclusive prefix over warps per expert
        int e2 = t >> 5, w2 = t & 31;
        int sacc = 0;
        for (int ww = 0; ww < w2; ww++) sacc += wcnt[ww][e2];
        woff[w2][e2] = sacc;
    }
    __syncthreads();
    if (t == 0) {
        int o = 0;
        for (int e2 = 0; e2 < E; e2++) {
            poff_s[e2] = o;
            int c = woff[31][e2] + wcnt[31][e2];
            o += (c + 15) & ~15;          // pad each expert to 16 rows
        }
        poff_s[E] = o;
        for (int i = 0; i <= E; i++) g_poff[i] = poff_s[i];
    }
    __syncthreads();
    for (int i = t; i < SPAD; i += 1024) { g_perm[i] = -1; g_wrow[i] = 0.f; }
    __syncthreads();
    int row = poff_s[e] + woff[w][e] + posw;
    g_perm[row] = t;
    g_wrow[row] = ew[t];
    if (t < NT) {
        int r0 = t * 16; int ee = -1;
        for (int e2 = 0; e2 < E; e2++)
            if (r0 >= poff_s[e2] && r0 < poff_s[e2+1]) ee = e2;
        g_etile[t] = ee;
    }
    if (t < 2 * E) {                      // softmax over M=16
        int which = t & 1, e2 = t >> 1;
        const float* L = (which ? glog : ulog) + e2 * MM;
        float mx = L[0];
        for (int m = 1; m < MM; m++) mx = fmaxf(mx, L[m]);
        float sum = 0.f, ex[MM];
        for (int m = 0; m < MM; m++) { ex[m] = __expf(L[m] - mx); sum += ex[m]; }
        float inv = 1.f / sum;
        for (int m = 0; m < MM; m++) g_alpha[which][e2][m] = ex[m] * inv;
    }
}

// ---------------- K2: mixed bases [E,D,R] = alpha @ bank ----------------
__global__ __launch_bounds__(256) void k_mixed(const float* __restrict__ ubank,
                                               const float* __restrict__ gbank) {
    __shared__ float al[2 * E * MM];      // 256 floats
    int t = threadIdx.x;
    al[t] = ((const float*)g_alpha)[t];
    __syncthreads();
    int r = t & 63, dl = t >> 6;
    int d = blockIdx.x * 4 + dl;
    float au[E], ag[E];
    #pragma unroll
    for (int e = 0; e < E; e++) { au[e] = 0.f; ag[e] = 0.f; }
    #pragma unroll
    for (int m = 0; m < MM; m++) {
        float bu = ubank[(m * D + d) * R + r];
        float bg = gbank[(m * D + d) * R + r];
        #pragma unroll
        for (int e = 0; e < E; e++) {
            au[e] += al[e * MM + m] * bu;
            ag[e] += al[E * MM + e * MM + m] * bg;
        }
    }
    #pragma unroll
    for (int e = 0; e < E; e++) {
        g_up_mixed  [(e * D + d) * R + r] = au[e];
        g_gate_mixed[(e * D + d) * R + r] = ag[e];
    }
}

// ---------------- K2b: transpose adapters [E,P,R] -> [E,R,P] ----------------
__global__ __launch_bounds__(256) void k_trans(const float* __restrict__ uA,
                                               const float* __restrict__ gA) {
    int e = blockIdx.z >> 1, which = blockIdx.z & 1;
    const float* src = which ? gA : uA;
    float* dst = which ? g_agt : g_aut;
    int p0 = blockIdx.x * 32, r0 = blockIdx.y * 32;
    __shared__ float sm[32][33];
    int tx = threadIdx.x, ty = threadIdx.y;
    for (int i = ty; i < 32; i += 8)
        sm[i][tx] = src[(e * PP + p0 + i) * R + r0 + tx];
    __syncthreads();
    for (int i = ty; i < 32; i += 8)
        dst[(e * R + r0 + i) * PP + p0 + tx] = sm[tx][i];
}

// ---------------- K3: t = X_gathered @ mixed (split-K=4, pipelined smem) ----------------
#define TCK 32
__global__ __launch_bounds__(256) void k_tproj(const float* __restrict__ x) {
    int tile = blockIdx.x;
    int e = g_etile[tile];
    if (e < 0) return;
    int split = blockIdx.y, d0 = split * 256;
    int base = tile * 16;
    __shared__ float xs[16][256];         // X tile, d-contiguous per row
    __shared__ float ms[3][TCK][128];     // mixed chunks: [d][col] col<64 up, >=64 gate
    __shared__ int ps[16];
    int t = threadIdx.x;
    if (t < 16) ps[t] = g_perm[base + t];
    __syncthreads();

    // X tile via cp.async (one group): 16 rows x 64 f4
    #pragma unroll
    for (int i = 0; i < 4; i++) {
        int q = t + i * 256;
        int row = q >> 6, c4 = q & 63;
        int s = ps[row];
        unsigned sa = (unsigned)__cvta_generic_to_shared(&xs[row][c4 * 4]);
        const float* src = &x[(size_t)(s < 0 ? 0 : s) * D + d0 + c4 * 4];
        int sz = (s >= 0) ? 16 : 0;
        asm volatile("cp.async.cg.shared.global [%0], [%1], 16, %2;"
                     :: "r"(sa), "l"(src), "r"(sz));
    }
    asm volatile("cp.async.commit_group;");

    const float* upb = g_up_mixed   + (size_t)(e * D + d0) * R;
    const float* gtb = g_gate_mixed + (size_t)(e * D + d0) * R;
    auto load_ms = [&](int ck, int buf) {
        #pragma unroll
        for (int i = 0; i < 4; i++) {
            int q = t + i * 256;          // 1024 f4 slots = 32 d x 32 f4
            int d = q >> 5, c = q & 31;   // c<16: up r-slot, c>=16: gate r-slot
            const float* src = (c < 16)
                ? upb + (size_t)(ck * TCK + d) * R + c * 4
                : gtb + (size_t)(ck * TCK + d) * R + (c - 16) * 4;
            unsigned sa = (unsigned)__cvta_generic_to_shared(&ms[buf][d][c * 4]);
            asm volatile("cp.async.cg.shared.global [%0], [%1], 16, 16;"
                         :: "r"(sa), "l"(src));
        }
        asm volatile("cp.async.commit_group;");
    };

    load_ms(0, 0);
    load_ms(1, 1);

    int col = t & 127, rg = t >> 7;       // col: 0-63 up, 64-127 gate; rg: row group
    float acc[8] = {};
    const int NCK = 256 / TCK;            // 8 chunks

    for (int ck = 0; ck < NCK; ck++) {
        if (ck + 2 < NCK) { asm volatile("cp.async.wait_group 1;"); }
        else              { asm volatile("cp.async.wait_group 0;"); }
        __syncthreads();
        if (ck + 2 < NCK) load_ms(ck + 2, (ck + 2) % 3);
        const float (*mb)[128] = ms[ck % 3];
        #pragma unroll
        for (int dd = 0; dd < TCK; dd += 4) {
            float4 xv[8];
            #pragma unroll
            for (int i = 0; i < 8; i++)
                xv[i] = *(const float4*)&xs[rg * 8 + i][ck * TCK + dd];
            #pragma unroll
            for (int j = 0; j < 4; j++) {
                float m = mb[dd + j][col];
                #pragma unroll
                for (int i = 0; i < 8; i++)
                    acc[i] += ((const float*)&xv[i])[j] * m;
            }
        }
        __syncthreads();
    }
    #pragma unroll
    for (int i = 0; i < 8; i++)
        g_tpart[(size_t)(split * SPAD + base + rg * 8 + i) * 128 + col] = acc[i];
}

// ---------------- K4: expert-persistent adapters + silu -> fp16 inter ----------
// grid (22, E, 2): z splits the expert's 32-row windows for SM load balance.
// dyn smem: au[64][128] | ag[64][128] | ts[32][128] = 81920 B
__global__ __launch_bounds__(256) void k_adapt() {
    extern __shared__ float sm4[];
    float* sau = sm4;                     // [64][128]
    float* sag = sm4 + 64 * 128;          // [64][128]
    float* ts  = sm4 + 2 * 64 * 128;      // [32][128]
    int e = blockIdx.y;
    int p0 = blockIdx.x * 128;
    int t = threadIdx.x;
    int r0 = g_poff[e], r1 = g_poff[e + 1];
    int nw = (r1 - r0 + 31) >> 5;
    int hh = blockIdx.z;
    int w0 = (nw * hh) >> 1, w1 = (nw * (hh + 1)) >> 1;
    if (w0 >= w1) return;

    const float* aup = g_aut + (size_t)e * R * PP + p0;
    const float* agp = g_agt + (size_t)e * R * PP + p0;
    #pragma unroll
    for (int i = 0; i < 8; i++) {
        int q = t + i * 256;              // over 2048 f4
        int r = q >> 5, c4 = q & 31;
        unsigned sa = (unsigned)__cvta_generic_to_shared(&sau[r * 128 + c4 * 4]);
        asm volatile("cp.async.cg.shared.global [%0], [%1], 16, 16;"
                     :: "r"(sa), "l"(aup + (size_t)r * PP + c4 * 4));
        unsigned sg = (unsigned)__cvta_generic_to_shared(&sag[r * 128 + c4 * 4]);
        asm volatile("cp.async.cg.shared.global [%0], [%1], 16, 16;"
                     :: "r"(sg), "l"(agp + (size_t)r * PP + c4 * 4));
    }
    asm volatile("cp.async.commit_group;");
    asm volatile("cp.async.wait_group 0;");
    __syncthreads();

    int c = t & 31, rg = t >> 5;          // c: 4 cols each; rg: warp -> 4 rows
    for (int wI = w0; wI < w1; wI++) {
        int base = r0 + wI * 32;
        __syncthreads();                  // ts write-after-read fence
        // reduce 4 split-K partials into ts (1024 f4 / 256 thr = 4 each)
        #pragma unroll
        for (int i = 0; i < 4; i++) {
            int q = t + i * 256;
            int row = q >> 5, c4 = q & 31;
            float4 acc = make_float4(0.f, 0.f, 0.f, 0.f);
            #pragma unroll
            for (int sp = 0; sp < 4; sp++) {
                float4 v = *(const float4*)&g_tpart[(size_t)(sp * SPAD + base + row) * 128 + c4 * 4];
                acc.x += v.x; acc.y += v.y; acc.z += v.z; acc.w += v.w;
            }
            *(float4*)&ts[row * 128 + c4 * 4] = acc;
        }
        __syncthreads();

        float accu[4][4] = {}, accg[4][4] = {};
        #pragma unroll 4
        for (int r = 0; r < R; r++) {
            float4 au  = *(const float4*)&sau[r * 128 + c * 4];
            float4 ag4 = *(const float4*)&sag[r * 128 + c * 4];
            #pragma unroll
            for (int i = 0; i < 4; i++) {
                float tu  = ts[(rg * 4 + i) * 128 + r];
                float tg2 = ts[(rg * 4 + i) * 128 + 64 + r];
                accu[i][0] += tu * au.x;  accu[i][1] += tu * au.y;
                accu[i][2] += tu * au.z;  accu[i][3] += tu * au.w;
                accg[i][0] += tg2 * ag4.x; accg[i][1] += tg2 * ag4.y;
                accg[i][2] += tg2 * ag4.z; accg[i][3] += tg2 * ag4.w;
            }
        }
        #pragma unroll
        for (int i = 0; i < 4; i++) {
            int row = base + rg * 4 + i;
            if (row < r1) {
                float sv[4];
                #pragma unroll
                for (int cc = 0; cc < 4; cc++) {
                    float gv = accg[i][cc], uv = accu[i][cc];
                    sv[cc] = uv * gv / (1.f + __expf(-gv));   // up * silu(gate)
                }
                __half2 h0 = __floats2half2_rn(sv[0], sv[1]);
                __half2 h1 = __floats2half2_rn(sv[2], sv[3]);
                uint2 u;
                u.x = *(unsigned*)&h0; u.y = *(unsigned*)&h1;
                *(uint2*)&g_inter[(size_t)row * PP + p0 + c * 4] = u;
            }
        }
    }
}

// ---------------- K5: routed down GEMM, fp16 mma m16n8k16, 4-stage ring ----------
// Block 256m x 64n, 512 thr (16 warps of 32m x 32n). B converted fp32->fp16
// in-kernel one stage ahead. dyn smem: Ash 4x12288 | Bsh 4x3072 | Braw 4x4096 = 77824 B
#define AS4   (256*48)      // A stage bytes (256 rows x 48B, 16 halfs data + pad)
#define BS4   (64*48)       // B stage bytes
#define BRAWF (64*16)       // B raw floats per stage
__global__ __launch_bounds__(512) void k_down(const float* __restrict__ down,
                                              float* __restrict__ out) {
    extern __shared__ char sm5[];
    char* AshP = sm5;
    char* BshP = sm5 + 4 * AS4;
    float* Braw = (float*)(sm5 + 4 * AS4 + 4 * BS4);
    uint32_t sA = s2u(sm5);
    uint32_t sB = sA + 4 * AS4;
    uint32_t sR = sB + 4 * BS4;
    int e = blockIdx.y;
    int r0 = g_poff[e], r1 = g_poff[e + 1];
    int d0 = blockIdx.x * 64;
    const float* Bg = down + ((size_t)e * D + d0) * PP;
    int t = threadIdx.x, lane = t & 31, gq = lane >> 2, tq = lane & 3;
    int w = t >> 5, wm = w & 7, wn = w >> 3;
    const int NKT = PP / 16;              // 176

    for (int rowBase = r0; rowBase < r1; rowBase += 256) {
        int rem = min(256, r1 - rowBase);
        const __half* Ag = g_inter + (size_t)rowBase * PP;

        auto issue = [&](int fs) {
            int buf = fs & 3, kk = fs * 16;
            {   // A: 256 rows x 2 chunks of 8 halfs
                int row = t >> 1, c = t & 1;
                bool ok = row < rem;
                const __half* src = ok ? (Ag + (size_t)row * PP + kk + c * 8) : Ag;
                uint32_t sa = sA + buf * AS4 + row * 48 + c * 16;
                int sz = ok ? 16 : 0;
                asm volatile("cp.async.cg.shared.global [%0], [%1], 16, %2;"
                             :: "r"(sa), "l"(src), "r"(sz));
            }
            if (t < 256) {  // B raw fp32: 64 rows x 4 chunks of 4 floats
                int row = t >> 2, c = t & 3;
                const float* src = Bg + (size_t)row * PP + kk + c * 4;
                uint32_t sa = sR + buf * (BRAWF * 4) + (row * 16 + c * 4) * 4;
                asm volatile("cp.async.cg.shared.global [%0], [%1], 16, 16;"
                             :: "r"(sa), "l"(src));
            }
            asm volatile("cp.async.commit_group;" ::: "memory");
        };
        auto convertB = [&](int cs) {
            int buf = cs & 3;
            if (t < 256) {
                int n = t >> 2, jf = t & 3;
                float4 v = *(const float4*)&Braw[buf * BRAWF + n * 16 + jf * 4];
                __half2 h0 = __floats2half2_rn(v.x, v.y);
                __half2 h1 = __floats2half2_rn(v.z, v.w);
                uint2 u; u.x = *(unsigned*)&h0; u.y = *(unsigned*)&h1;
                *(uint2*)(BshP + buf * BS4 + n * 48 + jf * 8) = u;
            }
        };

        issue(0); issue(1); issue(2);
        asm volatile("cp.async.wait_group 2;" ::: "memory");
        __syncthreads();
        convertB(0);

        float acc[2][4][4] = {};
        for (int kt = 0; kt < NKT; kt++) {
            if (kt + 1 < NKT) { asm volatile("cp.async.wait_group 1;" ::: "memory"); }
            else              { asm volatile("cp.async.wait_group 0;" ::: "memory"); }
            __syncthreads();
            if (kt + 3 < NKT) issue(kt + 3);
            if (kt + 1 < NKT) convertB(kt + 1);
            const char* Ab = AshP + (kt & 3) * AS4;
            const char* Bb = BshP + (kt & 3) * BS4;
            unsigned a[2][4], b[4][2];
            #pragma unroll
            for (int mf = 0; mf < 2; mf++) {
                int mr = wm * 32 + mf * 16 + gq;
                a[mf][0] = *(const unsigned*)(Ab +  mr      * 48 + tq * 4);
                a[mf][1] = *(const unsigned*)(Ab + (mr + 8) * 48 + tq * 4);
                a[mf][2] = *(const unsigned*)(Ab +  mr      * 48 + 16 + tq * 4);
                a[mf][3] = *(const unsigned*)(Ab + (mr + 8) * 48 + 16 + tq * 4);
            }
            #pragma unroll
            for (int nf = 0; nf < 4; nf++) {
                int nr = wn * 32 + nf * 8 + gq;
                b[nf][0] = *(const unsigned*)(Bb + nr * 48 + tq * 4);
                b[nf][1] = *(const unsigned*)(Bb + nr * 48 + 16 + tq * 4);
            }
            #pragma unroll
            for (int mf = 0; mf < 2; mf++)
                #pragma unroll
                for (int nf = 0; nf < 4; nf++)
                    asm volatile(
                        "mma.sync.aligned.m16n8k16.row.col.f32.f16.f16.f32 "
                        "{%0,%1,%2,%3}, {%4,%5,%6,%7}, {%8,%9}, {%0,%1,%2,%3};"
                        : "+f"(acc[mf][nf][0]), "+f"(acc[mf][nf][1]),
                          "+f"(acc[mf][nf][2]), "+f"(acc[mf][nf][3])
                        : "r"(a[mf][0]), "r"(a[mf][1]), "r"(a[mf][2]), "r"(a[mf][3]),
                          "r"(b[nf][0]), "r"(b[nf][1]));
        }
        // epilogue: scale by routing weight, scatter to original token rows
        #pragma unroll
        for (int mf = 0; mf < 2; mf++) {
            #pragma unroll
            for (int h = 0; h < 2; h++) {
                int m = wm * 32 + mf * 16 + gq + h * 8;
                if (m < rem) {
                    int s = g_perm[rowBase + m];
                    if (s >= 0) {
                        float wv = g_wrow[rowBase + m];
                        #pragma unroll
                        for (int nf = 0; nf < 4; nf++) {
                            int n = d0 + wn * 32 + nf * 8 + tq * 2;
                            float2 v;
                            v.x = acc[mf][nf][h * 2 + 0] * wv;
                            v.y = acc[mf][nf][h * 2 + 1] * wv;
                            *(float2*)&out[(size_t)s * D + n] = v;
                        }
                    }
                }
            }
        }
        __syncthreads();                  // reuse smem next rowBase iter
    }
}

// ---------------- launch ----------------
extern "C" void kernel_launch(void* const* d_in, const int* in_sizes, int n_in,
                              void* d_out, int out_size) {
    const float* x     = (const float*)d_in[0];
    const int*   eidx  = (const int*)  d_in[1];
    const float* ew    = (const float*)d_in[2];
    const float* uA    = (const float*)d_in[3];
    const float* gA    = (const float*)d_in[4];
    const float* ulog  = (const float*)d_in[5];
    const float* glog  = (const float*)d_in[6];
    const float* down  = (const float*)d_in[7];
    const float* ubank = (const float*)d_in[8];
    const float* gbank = (const float*)d_in[9];
    float* out = (float*)d_out;

    const int ADAPT_SMEM = (2 * 64 * 128 + 32 * 128) * 4;           // 81920
    const int DOWN_SMEM  = 4 * AS4 + 4 * BS4 + 4 * BRAWF * 4;       // 77824
    cudaFuncSetAttribute(k_adapt, cudaFuncAttributeMaxDynamicSharedMemorySize, ADAPT_SMEM);
    cudaFuncSetAttribute(k_down,  cudaFuncAttributeMaxDynamicSharedMemorySize, DOWN_SMEM);

    k_route<<<1, 1024>>>(eidx, ew, ulog, glog);
    k_mixed<<<256, 256>>>(ubank, gbank);
    k_trans<<<dim3(PP / 32, R / 32, 2 * E), dim3(32, 8)>>>(uA, gA);
    k_tproj<<<dim3(NT, 4), 256>>>(x);
    k_adapt<<<dim3(PP / 128, E, 2), 256, ADAPT_SMEM>>>();
    k_down<<<dim3(D / 64, E), 512, DOWN_SMEM>>>(down, out);
}